// round 10
// baseline (speedup 1.0000x reference)
#include <cuda_runtime.h>
#include <cuda_bf16.h>
#include <cfloat>

#define BATCH 4
#define NPTS 4096
#define NUP 16384
#define CDIM 64
#define EPSV 1e-6f

// Spatial grid: [-4,4]^3, h=0.25
#define GDIM 32
#define GCELLS (GDIM * GDIM * GDIM)     // 32768
#define TOTCELLS (BATCH * GCELLS)       // 131072
#define GLO (-4.0f)
#define GH 0.25f
#define GINV 4.0f
#define SCANB4 (TOTCELLS / 4096)        // 32 blocks per array (4 cells/thread)

// Scratch (__device__ globals; no cudaMalloc allowed)
__device__ float  g_G[BATCH * NPTS * CDIM];       // projected features F@W+b
__device__ int4   g_cnt4[2][TOTCELLS / 4];        // histograms [0]=pts [1]=queries
__device__ int4   g_start4[2][TOTCELLS / 4 + 1];  // exclusive scans (+sentinel)
__device__ int4   g_cur4[2][TOTCELLS / 4];        // scatter cursors
__device__ int    g_bsum2[2][64];                 // block sums
__device__ float4 g_tpos[BATCH * NPTS];
__device__ int    g_tcell[BATCH * NPTS];
__device__ float4 g_qpos[BATCH * NUP];
__device__ int    g_qcell[BATCH * NUP];
__device__ float4 g_spos[BATCH * NPTS];           // cell-sorted points
__device__ int    g_sidx[BATCH * NPTS];           // sorted -> original local idx
__device__ float4 g_sqpos[BATCH * NUP];           // cell-sorted queries
__device__ int    g_sqid[BATCH * NUP];            // sorted -> original global qid

#define G_CNT(ab)   ((int*)g_cnt4[ab])
#define G_START(ab) ((int*)g_start4[ab])
#define G_CUR(ab)   ((int*)g_cur4[ab])

__device__ __forceinline__ int cell_coord(float v) {
    int c = (int)floorf((v - GLO) * GINV);
    return min(max(c, 0), GDIM - 1);
}

// ---------------------------------------------------------------------------
// K0: zero both histograms (2*TOTCELLS ints = 65536 int4)
// ---------------------------------------------------------------------------
__global__ void zero_cnt_kernel() {
    int i = blockIdx.x * blockDim.x + threadIdx.x;
    g_cnt4[0][i] = make_int4(0, 0, 0, 0);          // [0] and [1] contiguous
    g_cnt4[1][i] = make_int4(0, 0, 0, 0);
}

// ---------------------------------------------------------------------------
// K1: histogram + stage for BOTH points (blocks [0,64)) and queries [64,320)
// ---------------------------------------------------------------------------
__global__ void hist_both_kernel(const float* __restrict__ pos,
                                 const float* __restrict__ pos_up) {
    int t = blockIdx.x * 256 + threadIdx.x;
    if (blockIdx.x < 64) {                 // points
        int i = t;
        int b = i >> 12;
        float x = pos[3 * i + 0];
        float y = pos[3 * i + 1];
        float z = pos[3 * i + 2];
        float n = x * x + y * y + z * z;
        g_tpos[i] = make_float4(x, y, z, n);
        int cell = b * GCELLS + ((cell_coord(z) * GDIM) + cell_coord(y)) * GDIM + cell_coord(x);
        g_tcell[i] = cell;
        atomicAdd(&G_CNT(0)[cell], 1);
    } else {                               // queries
        int i = t - 16384;
        int b = i >> 14;
        float x = pos_up[3 * i + 0];
        float y = pos_up[3 * i + 1];
        float z = pos_up[3 * i + 2];
        float n = x * x + y * y + z * z;
        g_qpos[i] = make_float4(x, y, z, n);
        int cell = b * GCELLS + ((cell_coord(z) * GDIM) + cell_coord(y)) * GDIM + cell_coord(x);
        g_qcell[i] = cell;
        atomicAdd(&G_CNT(1)[cell], 1);
    }
}

// ---------------------------------------------------------------------------
// K2a/b/c: exclusive scans (4 cells per thread via int4)
// ---------------------------------------------------------------------------
__device__ __forceinline__ int block_exscan_1024(int v, int* ws) {
    int lane = threadIdx.x & 31, w = threadIdx.x >> 5;
    int inc = v;
#pragma unroll
    for (int o = 1; o < 32; o <<= 1) {
        int n = __shfl_up_sync(0xffffffffu, inc, o);
        if (lane >= o) inc += n;
    }
    if (lane == 31) ws[w] = inc;
    __syncthreads();
    if (w == 0) {
        int t = ws[lane];
#pragma unroll
        for (int o = 1; o < 32; o <<= 1) {
            int n = __shfl_up_sync(0xffffffffu, t, o);
            if (lane >= o) t += n;
        }
        ws[lane] = t;
    }
    __syncthreads();
    return inc - v + (w > 0 ? ws[w - 1] : 0);
}

__global__ __launch_bounds__(1024) void scan_a_kernel() {   // grid 2*SCANB4
    __shared__ int ws[32];
    int ab = blockIdx.x >= SCANB4;
    int blk = blockIdx.x - ab * SCANB4;
    int g = blk * 1024 + threadIdx.x;
    int4 v = g_cnt4[ab][g];
    int s = v.x + v.y + v.z + v.w;
    int ex = block_exscan_1024(s, ws);
    int4 o;
    o.x = ex;
    o.y = ex + v.x;
    o.z = o.y + v.y;
    o.w = o.z + v.z;
    g_start4[ab][g] = o;
    if (threadIdx.x == 1023) g_bsum2[ab][blk] = ex + s;
}

__global__ __launch_bounds__(1024) void scan_b_kernel() {   // grid 2
    __shared__ int ws[32];
    int ab = blockIdx.x;
    int v = (threadIdx.x < SCANB4) ? g_bsum2[ab][threadIdx.x] : 0;
    int ex = block_exscan_1024(v, ws);
    if (threadIdx.x < SCANB4) g_bsum2[ab][threadIdx.x] = ex;
}

__global__ __launch_bounds__(1024) void scan_c_kernel() {   // grid 2*SCANB4
    int ab = blockIdx.x >= SCANB4;
    int blk = blockIdx.x - ab * SCANB4;
    int g = blk * 1024 + threadIdx.x;
    int add = g_bsum2[ab][blk];
    int4 o = g_start4[ab][g];
    o.x += add; o.y += add; o.z += add; o.w += add;
    g_start4[ab][g] = o;
    g_cur4[ab][g] = o;
    if (g == TOTCELLS / 4 - 1)
        G_START(ab)[TOTCELLS] = ab ? (BATCH * NUP) : (BATCH * NPTS);
}

// ---------------------------------------------------------------------------
// K3: scatter both into cell-sorted order
// ---------------------------------------------------------------------------
__global__ void scatter_both_kernel() {
    int t = blockIdx.x * 256 + threadIdx.x;
    if (blockIdx.x < 64) {
        int i = t;
        int dst = atomicAdd(&G_CUR(0)[g_tcell[i]], 1);
        g_spos[dst] = g_tpos[i];
        g_sidx[dst] = i & (NPTS - 1);
    } else {
        int i = t - 16384;
        int dst = atomicAdd(&G_CUR(1)[g_qcell[i]], 1);
        g_sqpos[dst] = g_qpos[i];
        g_sqid[dst] = i;
    }
}

// ---------------------------------------------------------------------------
// K4: projection G = F @ W + b
// ---------------------------------------------------------------------------
#define PROJ_ROWS 32

__global__ __launch_bounds__(64) void proj_kernel(
    const float* __restrict__ feature,
    const float* __restrict__ W,
    const float* __restrict__ bias)
{
    __shared__ float frow[PROJ_ROWS * CDIM];
    const int d = threadIdx.x;
    const int row0 = blockIdx.x * PROJ_ROWS;

    float wcol[CDIM];
#pragma unroll
    for (int k = 0; k < CDIM; k++) wcol[k] = __ldg(&W[k * CDIM + d]);
    const float bd = __ldg(&bias[d]);

    const float* fsrc = feature + (size_t)row0 * CDIM;
    for (int i = threadIdx.x; i < PROJ_ROWS * CDIM; i += 64)
        frow[i] = fsrc[i];
    __syncthreads();

    for (int r = 0; r < PROJ_ROWS; r++) {
        float a0 = bd, a1 = 0.f, a2 = 0.f, a3 = 0.f;
        const float* fr = &frow[r * CDIM];
#pragma unroll
        for (int k = 0; k < CDIM; k += 4) {
            a0 = fmaf(fr[k + 0], wcol[k + 0], a0);
            a1 = fmaf(fr[k + 1], wcol[k + 1], a1);
            a2 = fmaf(fr[k + 2], wcol[k + 2], a2);
            a3 = fmaf(fr[k + 3], wcol[k + 3], a3);
        }
        g_G[(size_t)(row0 + r) * CDIM + d] = (a0 + a1) + (a2 + a3);
    }
}

// ---------------------------------------------------------------------------
__device__ __forceinline__ void ins3(float s, int idx,
                                     float& d0, float& d1, float& d2,
                                     int& i0, int& i1, int& i2)
{
    if (s < d2) {
        if (s < d1) {
            d2 = d1; i2 = i1;
            if (s < d0) { d1 = d0; i1 = i0; d0 = s; i0 = idx; }
            else        { d1 = s;  i1 = idx; }
        } else {
            d2 = s; i2 = idx;
        }
    }
}

// ---------------------------------------------------------------------------
// K5: 4-threads-per-query 3-NN + fused apply.
// Phase 1: count-only adaptive radius (prefix diffs; no point data).
// Phase 2: single point scan at chosen r; exact face-bound; rare expansion.
// Phase 3: each sub blends its 16 output channels (apply fused).
// ---------------------------------------------------------------------------
#define RB 4

__global__ __launch_bounds__(256) void query_apply_kernel(float* __restrict__ out)
{
    const int lane = threadIdx.x & 31;
    const int warp = threadIdx.x >> 5;
    const int sub  = lane >> 3;          // 0..3
    const int qi   = lane & 7;           // 0..7
    const int t = blockIdx.x * 64 + warp * 8 + qi;   // sorted query index
    const float4 qp = __ldg(&g_sqpos[t]);
    const int qid = __ldg(&g_sqid[t]);
    const int b = qid >> 14;

    const float qx = qp.x, qy = qp.y, qz = qp.z, qn = qp.w;
    const float qx2 = -2.0f * qx, qy2 = -2.0f * qy, qz2 = -2.0f * qz;
    const int cx = cell_coord(qx), cy = cell_coord(qy), cz = cell_coord(qz);
    const int* __restrict__ startP = G_START(0);

    // ---- Phase 1: pick starting radius from cube counts only ----
    int r = 1;
    bool cdone = false;
    while (true) {
        int n = 0;
        int xlo = 0, xhi = 0, ylo = 0, yhi = 0, zlo = 0, zhi = 0;
        if (!cdone) {
            xlo = max(cx - r, 0); xhi = min(cx + r, GDIM - 1);
            ylo = max(cy - r, 0); yhi = min(cy + r, GDIM - 1);
            zlo = max(cz - r, 0); zhi = min(cz + r, GDIM - 1);
            const int ny = yhi - ylo + 1;
            const int nrows = (zhi - zlo + 1) * ny;
            for (int base = sub; base < nrows; base += 4) {
                const int zz = zlo + base / ny;
                const int yy = ylo + (base - (base / ny) * ny);
                const int row = b * GCELLS + ((zz * GDIM) + yy) * GDIM;
                n += __ldg(&startP[row + xhi + 1]) - __ldg(&startP[row + xlo]);
            }
        }
        n += __shfl_xor_sync(0xffffffffu, n, 8);
        n += __shfl_xor_sync(0xffffffffu, n, 16);
        if (!cdone) {
            bool covered = (xlo == 0) && (xhi == GDIM - 1) &&
                           (ylo == 0) && (yhi == GDIM - 1) &&
                           (zlo == 0) && (zhi == GDIM - 1);
            float rc = (float)(2 * r + 1);
            float T = 6.0f * rc * rc * rc / (4.18879f * (float)r * (float)r * (float)r);
            if (covered || (float)n >= T) {
                cdone = true;
            } else {
                int rn;
                if (n == 0) rn = 2 * r;
                else {
                    rn = (int)ceilf((float)r * cbrtf(T / (float)n));
                    rn = max(rn, r + 1);
                    rn = min(rn, 2 * r);
                }
                r = min(rn, GDIM);
            }
        }
        if (__all_sync(0xffffffffu, cdone)) break;
    }

    // ---- Phase 2: scan points at radius r; exact stop; rare expansion ----
    float d0 = FLT_MAX, d1 = FLT_MAX, d2 = FLT_MAX;
    int   i0 = 0, i1 = 0, i2 = 0;
    bool done = false;

    while (true) {
        if (!done) {
            d0 = FLT_MAX; d1 = FLT_MAX; d2 = FLT_MAX;
            const int xlo = max(cx - r, 0), xhi = min(cx + r, GDIM - 1);
            const int ylo = max(cy - r, 0), yhi = min(cy + r, GDIM - 1);
            const int zlo = max(cz - r, 0), zhi = min(cz + r, GDIM - 1);
            const int ny = yhi - ylo + 1;
            const int nrows = (zhi - zlo + 1) * ny;

            for (int base = sub; base < nrows; base += 4 * RB) {
                int rs[RB], re[RB];
#pragma unroll
                for (int k = 0; k < RB; k++) {
                    const int ridx = base + k * 4;
                    if (ridx < nrows) {
                        const int zz = zlo + ridx / ny;
                        const int yy = ylo + (ridx - (ridx / ny) * ny);
                        const int row = b * GCELLS + ((zz * GDIM) + yy) * GDIM;
                        rs[k] = __ldg(&startP[row + xlo]);
                        re[k] = __ldg(&startP[row + xhi + 1]);
                    } else { rs[k] = 0; re[k] = 0; }
                }
#pragma unroll
                for (int k = 0; k < RB; k++) {
                    for (int i = rs[k]; i < re[k]; i++) {
                        float4 p = __ldg(&g_spos[i]);
                        float sv = fmaf(qx2, p.x, fmaf(qy2, p.y, fmaf(qz2, p.z, p.w)));
                        if (sv < d2) ins3(sv, i, d0, d1, d2, i0, i1, i2);
                    }
                }
            }
        }

        // merge across 4 subs (all lanes shuffle)
#pragma unroll
        for (int off = 8; off <= 16; off <<= 1) {
            float e0 = __shfl_xor_sync(0xffffffffu, d0, off);
            float e1 = __shfl_xor_sync(0xffffffffu, d1, off);
            float e2 = __shfl_xor_sync(0xffffffffu, d2, off);
            int   f0 = __shfl_xor_sync(0xffffffffu, i0, off);
            int   f1 = __shfl_xor_sync(0xffffffffu, i1, off);
            int   f2 = __shfl_xor_sync(0xffffffffu, i2, off);
            if (!done) {
                ins3(e0, f0, d0, d1, d2, i0, i1, i2);
                ins3(e1, f1, d0, d1, d2, i0, i1, i2);
                ins3(e2, f2, d0, d1, d2, i0, i1, i2);
            }
        }

        if (!done) {
            float rb = FLT_MAX;
            bool covered = true;
            if (cx - r > 0)        { rb = fminf(rb, qx - (GLO + (cx - r) * GH));     covered = false; }
            if (cx + r < GDIM - 1) { rb = fminf(rb, (GLO + (cx + r + 1) * GH) - qx); covered = false; }
            if (cy - r > 0)        { rb = fminf(rb, qy - (GLO + (cy - r) * GH));     covered = false; }
            if (cy + r < GDIM - 1) { rb = fminf(rb, (GLO + (cy + r + 1) * GH) - qy); covered = false; }
            if (cz - r > 0)        { rb = fminf(rb, qz - (GLO + (cz - r) * GH));     covered = false; }
            if (cz + r < GDIM - 1) { rb = fminf(rb, (GLO + (cz + r + 1) * GH) - qz); covered = false; }

            done = covered || (d2 + qn <= rb * rb * 0.99999f);
            if (!done) r++;
        }
        if (__all_sync(0xffffffffu, done)) break;
    }

    // ---- Phase 3: fused apply — each sub handles 16 channels ----
    const float w0 = 1.0f / ((d0 + qn) + EPSV);
    const float w1 = 1.0f / ((d1 + qn) + EPSV);
    const float w2 = 1.0f / ((d2 + qn) + EPSV);
    const float inv = 1.0f / (w0 + w1 + w2);
    const float wn0 = w0 * inv, wn1 = w1 * inv, wn2 = w2 * inv;

    const int j0 = __ldg(&g_sidx[i0]);
    const int j1 = __ldg(&g_sidx[i1]);
    const int j2 = __ldg(&g_sidx[i2]);

    const float4* G4 = reinterpret_cast<const float4*>(g_G);
    const float4* r0 = G4 + (size_t)(b * NPTS + j0) * (CDIM / 4) + sub * 4;
    const float4* r1 = G4 + (size_t)(b * NPTS + j1) * (CDIM / 4) + sub * 4;
    const float4* r2 = G4 + (size_t)(b * NPTS + j2) * (CDIM / 4) + sub * 4;
    float4* out4 = reinterpret_cast<float4*>(out) + (size_t)qid * (CDIM / 4) + sub * 4;

#pragma unroll
    for (int k = 0; k < 4; k++) {
        float4 a = __ldg(&r0[k]);
        float4 c = __ldg(&r1[k]);
        float4 e = __ldg(&r2[k]);
        float4 o;
        o.x = fmaxf(0.f, fmaf(wn0, a.x, fmaf(wn1, c.x, wn2 * e.x)));
        o.y = fmaxf(0.f, fmaf(wn0, a.y, fmaf(wn1, c.y, wn2 * e.y)));
        o.z = fmaxf(0.f, fmaf(wn0, a.z, fmaf(wn1, c.z, wn2 * e.z)));
        o.w = fmaxf(0.f, fmaf(wn0, a.w, fmaf(wn1, c.w, wn2 * e.w)));
        out4[k] = o;
    }
}

// ---------------------------------------------------------------------------
extern "C" void kernel_launch(void* const* d_in, const int* in_sizes, int n_in,
                              void* d_out, int out_size)
{
    const float* feature = (const float*)d_in[0];   // (4, 4096, 64)
    const float* pos     = (const float*)d_in[1];   // (4, 4096, 3)
    const float* pos_up  = (const float*)d_in[2];   // (4, 16384, 3)
    const float* W       = (const float*)d_in[3];   // (64, 64)
    const float* bias    = (const float*)d_in[4];   // (64,)
    float* out = (float*)d_out;                     // (4, 16384, 64)

    zero_cnt_kernel<<<128, 256>>>();
    hist_both_kernel<<<320, 256>>>(pos, pos_up);
    proj_kernel<<<BATCH * NPTS / PROJ_ROWS, 64>>>(feature, W, bias);
    scan_a_kernel<<<2 * SCANB4, 1024>>>();
    scan_b_kernel<<<2, 1024>>>();
    scan_c_kernel<<<2 * SCANB4, 1024>>>();
    scatter_both_kernel<<<320, 256>>>();

    query_apply_kernel<<<BATCH * NUP / 64, 256>>>(out);
}